// round 8
// baseline (speedup 1.0000x reference)
#include <cuda_runtime.h>
#include <cstdint>

// Problem constants
#define Bn  1024
#define Sn  128
#define En  256
#define Hn  8
#define Dn  64
#define HDn 512

// Scratch: Xt = X pre-converted to tf32 bits (128 MiB), Wt = transposed +
// converted weights (2 MiB). Q/K/V never touch global memory anymore.
__device__ float g_Xt[33554432];
__device__ float g_Wt[2048 * 256];

// ---------------------------------------------------------------------------
// Helpers. tcgen05 unusable (harness PTX target sm_103, no 'a' suffix) -> the
// tensor path is arch-portable mma.sync (HMMA on sm_103a).
// ---------------------------------------------------------------------------
__device__ __forceinline__ uint32_t smem_u32(const void* p) {
    uint32_t a;
    asm("{ .reg .u64 t; cvta.to.shared.u64 t, %1; cvt.u32.u64 %0, t; }"
        : "=r"(a) : "l"(p));
    return a;
}
__device__ __forceinline__ uint32_t f2tf32(float x) {
    uint32_t r;
    asm("cvt.rna.tf32.f32 %0, %1;" : "=r"(r) : "f"(x));
    return r;
}
__device__ __forceinline__ void mma_tf32(float* c,
                                         const uint32_t* a,
                                         const uint32_t* b) {
    asm volatile(
        "mma.sync.aligned.m16n8k8.row.col.f32.tf32.tf32.f32 "
        "{%0,%1,%2,%3}, {%4,%5,%6,%7}, {%8,%9}, {%0,%1,%2,%3};"
        : "+f"(c[0]), "+f"(c[1]), "+f"(c[2]), "+f"(c[3])
        : "r"(a[0]), "r"(a[1]), "r"(a[2]), "r"(a[3]),
          "r"(b[0]), "r"(b[1]));
}
__device__ __forceinline__ void cpa16(uint32_t saddr, const void* g) {
    asm volatile("cp.async.cg.shared.global [%0], [%1], 16;"
                 :: "r"(saddr), "l"(g) : "memory");
}
#define CP_COMMIT() asm volatile("cp.async.commit_group;" ::: "memory")
#define CP_WAIT(n)  asm volatile("cp.async.wait_group %0;" :: "n"(n) : "memory")

// =============================================================================
// Kernel 0a: convert X -> tf32 bits (RNA) in g_Xt.
// =============================================================================
__global__ void xconv_kernel(const float4* __restrict__ X)
{
    uint4* dst = (uint4*)g_Xt;
#pragma unroll
    for (int j = 0; j < 4; ++j) {
        const size_t i = (size_t)blockIdx.x * 1024 + j * 256 + threadIdx.x;
        float4 v = X[i];
        dst[i] = make_uint4(f2tf32(v.x), f2tf32(v.y), f2tf32(v.z), f2tf32(v.w));
    }
}

// =============================================================================
// Kernel 0b: weight transpose + tf32 convert. Wt[w*512 + n][k] = tf32(W_w[k][n])
// =============================================================================
__global__ void wtrans_kernel(const float* __restrict__ Wq,
                              const float* __restrict__ Wk,
                              const float* __restrict__ Wv,
                              const float* __restrict__ Wr)
{
    __shared__ float t[32][33];
    const int wsel = blockIdx.z;
    const float* W = (wsel == 0) ? Wq : (wsel == 1) ? Wk : (wsel == 2) ? Wv : Wr;
    const int n0 = blockIdx.x * 32, k0 = blockIdx.y * 32;
    const int tx = threadIdx.x, ty = threadIdx.y;
#pragma unroll
    for (int i = 0; i < 32; i += 8)
        t[ty + i][tx] = W[(size_t)(k0 + ty + i) * HDn + n0 + tx];
    __syncthreads();
    uint32_t* Wt = (uint32_t*)g_Wt;
#pragma unroll
    for (int i = 0; i < 32; i += 8)
        Wt[(size_t)(wsel * HDn + n0 + ty + i) * En + k0 + tx] = f2tf32(t[tx][ty + i]);
}

// =============================================================================
// Fused kernel: one CTA per (b,h), 256 threads, 8 warps.
//  Stage 1: two GEMM passes ({Q,K} then {V,R}), each 128x64x256, k-chunks of
//           16, 3-stage cp.async pipeline, warp grid 4(m) x 2(n), tile 32x32.
//           Outputs go to smem only (tf32 bits; R kept fp32).
//  Stage 2: attention (round-7 validated fragment paths): QK^T, quad-local
//           softmax, P (unnormalized exp, tf32) overlaying SQ/SK, PV.
//  Epilogue: out = relu(O*inv + R). Single global write, no global read.
// =============================================================================
constexpr int PX     = 20;                       // stage-1 chunk pitch (u32)
constexpr int SLOT_U = 128 * PX + 2 * 64 * PX;   // 5120 u32 = 20480 B per slot
constexpr int PK  = 68;                          // SQ/SK pitch
constexpr int PV  = 72;                          // SV pitch
constexpr int PR  = 68;                          // SR pitch
constexpr int PPs = 132;                         // SP pitch
constexpr int OFF_SQ = 3 * SLOT_U;               // 15360
constexpr int OFF_SK = OFF_SQ + 128 * PK;        // 24064
constexpr int OFF_SV = OFF_SK + 128 * PK;        // 32768
constexpr int OFF_SR = OFF_SV + 128 * PV;        // 41984
constexpr int SMEM_U = OFF_SR + 128 * PR;        // 50688 u32 = 202752 B
// SP overlays SQ+SK: 128*132 = 16896 u32 <= 2*128*68 = 17408 u32  ✓

__global__ __launch_bounds__(256)
void fused_mma(float* __restrict__ out)
{
    extern __shared__ uint32_t sm[];
    const uint32_t sb = smem_u32(sm);

    const int tid  = threadIdx.x;
    const int wid  = tid >> 5;
    const int lane = tid & 31;
    const int g    = lane >> 2;
    const int tg   = lane & 3;
    const int h = blockIdx.x, b = blockIdx.y;

    const float4* Xb4 = (const float4*)(g_Xt + (size_t)b * Sn * En);
    const float4* W4  = (const float4*)g_Wt;

    // stage-1 warp grid: 4(m) x 2(n); warp tile 32x32
    const int wm = wid >> 1;
    const int wn = wid & 1;

    // cp.async per-thread coords: X chunk = 512 float4 (128 rows x 4),
    // W chunk = 512 float4 (2 weights x 64 rows x 4). 4 cp16 per thread.
    const int xr = tid >> 2;        // 0..63
    const int xk = tid & 3;         // 0..3

    auto issue = [&](int c, int wb0, int wb1) {
        const int s = c - (c >= 3 ? 3 * ((unsigned)c / 3u) : 0); // c % 3
        const uint32_t xs = sb + (uint32_t)s * SLOT_U * 4;
        const uint32_t ws = xs + 128 * PX * 4;
        // X rows xr and xr+64
        cpa16(xs + (uint32_t)(xr * PX + xk * 4) * 4,
              Xb4 + xr * 64 + c * 4 + xk);
        cpa16(xs + (uint32_t)((xr + 64) * PX + xk * 4) * 4,
              Xb4 + (xr + 64) * 64 + c * 4 + xk);
        // weights 0 and 1, row xr (0..63)
        cpa16(ws + (uint32_t)(xr * PX + xk * 4) * 4,
              W4 + (size_t)(wb0 + xr) * 64 + c * 4 + xk);
        cpa16(ws + (uint32_t)(64 * PX + xr * PX + xk * 4) * 4,
              W4 + (size_t)(wb1 + xr) * 64 + c * 4 + xk);
        CP_COMMIT();
    };

    const int wbase[4] = { h * Dn, HDn + h * Dn, 2 * HDn + h * Dn, 3 * HDn + h * Dn };

#pragma unroll 1
    for (int pass = 0; pass < 2; ++pass) {
        const int wb0 = wbase[pass * 2];
        const int wb1 = wbase[pass * 2 + 1];

        float acc2[2][2][4][4];
#pragma unroll
        for (int w2 = 0; w2 < 2; ++w2)
#pragma unroll
            for (int mt = 0; mt < 2; ++mt)
#pragma unroll
                for (int nt = 0; nt < 4; ++nt)
#pragma unroll
                    for (int j = 0; j < 4; ++j) acc2[w2][mt][nt][j] = 0.f;

        issue(0, wb0, wb1);
        issue(1, wb0, wb1);

#pragma unroll 1
        for (int c = 0; c < 16; ++c) {
            if (c < 15) { CP_WAIT(1); } else { CP_WAIT(0); }
            __syncthreads();
            if (c < 14) issue(c + 2, wb0, wb1);

            const int s = c % 3;
            const uint32_t* SX  = sm + s * SLOT_U;
            const uint32_t* SW0 = SX + 128 * PX;
            const uint32_t* SW1 = SW0 + 64 * PX;
#pragma unroll
            for (int ks = 0; ks < 2; ++ks) {
                const int k0 = ks * 8;
                uint32_t af[2][4];
#pragma unroll
                for (int mt = 0; mt < 2; ++mt) {
                    const int base = (wm * 32 + mt * 16 + g) * PX + k0 + tg;
                    af[mt][0] = SX[base];
                    af[mt][1] = SX[base + 8 * PX];
                    af[mt][2] = SX[base + 4];
                    af[mt][3] = SX[base + 8 * PX + 4];
                }
                uint32_t bf[2][4][2];
#pragma unroll
                for (int nt = 0; nt < 4; ++nt) {
                    const int nb = (wn * 32 + nt * 8 + g) * PX + k0 + tg;
                    bf[0][nt][0] = SW0[nb];
                    bf[0][nt][1] = SW0[nb + 4];
                    bf[1][nt][0] = SW1[nb];
                    bf[1][nt][1] = SW1[nb + 4];
                }
#pragma unroll
                for (int w2 = 0; w2 < 2; ++w2)
#pragma unroll
                    for (int mt = 0; mt < 2; ++mt)
#pragma unroll
                        for (int nt = 0; nt < 4; ++nt)
                            mma_tf32(acc2[w2][mt][nt], af[mt], bf[w2][nt]);
            }
        }

        // store pass outputs to smem tiles
#pragma unroll
        for (int mt = 0; mt < 2; ++mt) {
            const int row = wm * 32 + mt * 16 + g;
#pragma unroll
            for (int nt = 0; nt < 4; ++nt) {
                const int col = wn * 32 + nt * 8 + tg * 2;
                const float* a0 = acc2[0][mt][nt];
                const float* a1 = acc2[1][mt][nt];
                if (pass == 0) {
                    // Q -> SQ (tf32), K -> SK (tf32)
                    *(uint2*)&sm[OFF_SQ + row * PK + col] =
                        make_uint2(f2tf32(a0[0]), f2tf32(a0[1]));
                    *(uint2*)&sm[OFF_SQ + (row + 8) * PK + col] =
                        make_uint2(f2tf32(a0[2]), f2tf32(a0[3]));
                    *(uint2*)&sm[OFF_SK + row * PK + col] =
                        make_uint2(f2tf32(a1[0]), f2tf32(a1[1]));
                    *(uint2*)&sm[OFF_SK + (row + 8) * PK + col] =
                        make_uint2(f2tf32(a1[2]), f2tf32(a1[3]));
                } else {
                    // V -> SV (tf32), R -> SR (raw fp32)
                    *(uint2*)&sm[OFF_SV + row * PV + col] =
                        make_uint2(f2tf32(a0[0]), f2tf32(a0[1]));
                    *(uint2*)&sm[OFF_SV + (row + 8) * PV + col] =
                        make_uint2(f2tf32(a0[2]), f2tf32(a0[3]));
                    *(uint2*)&sm[OFF_SR + row * PR + col] =
                        make_uint2(__float_as_uint(a1[0]), __float_as_uint(a1[1]));
                    *(uint2*)&sm[OFF_SR + (row + 8) * PR + col] =
                        make_uint2(__float_as_uint(a1[2]), __float_as_uint(a1[3]));
                }
            }
        }
        __syncthreads();   // outputs visible; pipeline slots safe for next pass
    }

    // ======================= Stage 2: attention =============================
    const uint32_t* SQ = sm + OFF_SQ;
    const uint32_t* SK = sm + OFF_SK;
    const uint32_t* SV = sm + OFF_SV;
    uint32_t*       SP = sm + OFF_SQ;   // overlays SQ+SK

    // ---- S = Q K^T : warp owns rows wid*16..+16, all 128 cols ----
    float acc[16][4];
#pragma unroll
    for (int nt = 0; nt < 16; ++nt)
#pragma unroll
        for (int j = 0; j < 4; ++j) acc[nt][j] = 0.f;

    const uint32_t* Arow = SQ + (wid * 16 + g) * PK;
#pragma unroll
    for (int ks = 0; ks < 8; ++ks) {
        const int k0 = ks * 8;
        uint32_t af[4];
        af[0] = Arow[k0 + tg];
        af[1] = Arow[8 * PK + k0 + tg];
        af[2] = Arow[k0 + tg + 4];
        af[3] = Arow[8 * PK + k0 + tg + 4];
#pragma unroll
        for (int nt = 0; nt < 16; ++nt) {
            const uint32_t* Bp = SK + (nt * 8 + g) * PK + k0 + tg;
            uint32_t bf[2] = { Bp[0], Bp[4] };
            mma_tf32(acc[nt], af, bf);
        }
    }

    // ---- softmax rows r0 = wid*16+g, r1 = r0+8 (quad-local shfl) ----
    float m0 = -1e30f, m1 = -1e30f;
#pragma unroll
    for (int nt = 0; nt < 16; ++nt) {
        m0 = fmaxf(m0, fmaxf(acc[nt][0], acc[nt][1]));
        m1 = fmaxf(m1, fmaxf(acc[nt][2], acc[nt][3]));
    }
#pragma unroll
    for (int off = 2; off >= 1; off >>= 1) {
        m0 = fmaxf(m0, __shfl_xor_sync(0xffffffffu, m0, off));
        m1 = fmaxf(m1, __shfl_xor_sync(0xffffffffu, m1, off));
    }
    float s0 = 0.f, s1 = 0.f;
#pragma unroll
    for (int nt = 0; nt < 16; ++nt) {
        acc[nt][0] = __expf(acc[nt][0] - m0);
        acc[nt][1] = __expf(acc[nt][1] - m0);
        acc[nt][2] = __expf(acc[nt][2] - m1);
        acc[nt][3] = __expf(acc[nt][3] - m1);
        s0 += acc[nt][0] + acc[nt][1];
        s1 += acc[nt][2] + acc[nt][3];
    }
#pragma unroll
    for (int off = 2; off >= 1; off >>= 1) {
        s0 += __shfl_xor_sync(0xffffffffu, s0, off);
        s1 += __shfl_xor_sync(0xffffffffu, s1, off);
    }
    const float inv0 = 1.0f / s0;
    const float inv1 = 1.0f / s1;

    __syncthreads();   // all warps done reading SQ/SK before SP overlays them

    const int r0 = wid * 16 + g;
#pragma unroll
    for (int nt = 0; nt < 16; ++nt) {
        const int cl = nt * 8 + tg * 2;
        *(uint2*)&SP[r0 * PPs + cl] =
            make_uint2(f2tf32(acc[nt][0]), f2tf32(acc[nt][1]));
        *(uint2*)&SP[(r0 + 8) * PPs + cl] =
            make_uint2(f2tf32(acc[nt][2]), f2tf32(acc[nt][3]));
    }
    __syncthreads();

    // ---- O = P V ----
    float oacc[8][4];
#pragma unroll
    for (int nt = 0; nt < 8; ++nt)
#pragma unroll
        for (int j = 0; j < 4; ++j) oacc[nt][j] = 0.f;

    const uint32_t* Ap = SP + (wid * 16 + g) * PPs;
#pragma unroll
    for (int ks = 0; ks < 16; ++ks) {
        const int k0 = ks * 8;
        uint32_t af[4];
        af[0] = Ap[k0 + tg];
        af[1] = Ap[8 * PPs + k0 + tg];
        af[2] = Ap[k0 + tg + 4];
        af[3] = Ap[8 * PPs + k0 + tg + 4];
#pragma unroll
        for (int nt = 0; nt < 8; ++nt) {
            uint32_t bf[2];
            bf[0] = SV[(k0 + tg) * PV + nt * 8 + g];
            bf[1] = SV[(k0 + tg + 4) * PV + nt * 8 + g];
            mma_tf32(oacc[nt], af, bf);
        }
    }

    // ---- epilogue: out = relu(O*inv + R); single global write ----
    float* op = out + ((size_t)b * Sn) * HDn + h * Dn;
#pragma unroll
    for (int nt = 0; nt < 8; ++nt) {
        const int d = nt * 8 + tg * 2;
        uint2 rr0 = *(uint2*)&sm[OFF_SR + r0 * PR + d];
        uint2 rr1 = *(uint2*)&sm[OFF_SR + (r0 + 8) * PR + d];
        float x0 = __uint_as_float(rr0.x) + oacc[nt][0] * inv0;
        float x1 = __uint_as_float(rr0.y) + oacc[nt][1] * inv0;
        float x2 = __uint_as_float(rr1.x) + oacc[nt][2] * inv1;
        float x3 = __uint_as_float(rr1.y) + oacc[nt][3] * inv1;
        *(float2*)(op + (size_t)r0 * HDn + d) =
            make_float2(fmaxf(x0, 0.f), fmaxf(x1, 0.f));
        *(float2*)(op + (size_t)(r0 + 8) * HDn + d) =
            make_float2(fmaxf(x2, 0.f), fmaxf(x3, 0.f));
    }
}

// =============================================================================
extern "C" void kernel_launch(void* const* d_in, const int* in_sizes, int n_in,
                              void* d_out, int out_size)
{
    const float* X  = (const float*)d_in[0];
    const float* Wq = (const float*)d_in[1];
    const float* Wk = (const float*)d_in[2];
    const float* Wv = (const float*)d_in[3];
    const float* Wr = (const float*)d_in[4];
    float* out = (float*)d_out;

    const int fused_smem = SMEM_U * (int)sizeof(uint32_t);   // 202752
    cudaFuncSetAttribute(fused_mma,
                         cudaFuncAttributeMaxDynamicSharedMemorySize, fused_smem);

    xconv_kernel<<<8192, 256>>>((const float4*)X);
    wtrans_kernel<<<dim3(16, 8, 4), dim3(32, 8)>>>(Wq, Wk, Wv, Wr);
    fused_mma<<<dim3(8, 1024), 256, fused_smem>>>(out);
}

// round 10
// speedup vs baseline: 1.1508x; 1.1508x over previous
#include <cuda_runtime.h>
#include <cstdint>

// Problem constants
#define Bn  1024
#define Sn  128
#define En  256
#define Hn  8
#define Dn  64
#define HDn 512

// Scratch (tf32 bit patterns in float arrays): Q,K,V per-(b,h) [128x64] tiles,
// Xt = pre-converted inputs, Wt = transposed + converted weights.
__device__ float g_Q[67108864];
__device__ float g_K[67108864];
__device__ float g_V[67108864];
__device__ float g_Xt[33554432];
__device__ float g_Wt[2048 * 256];

// ---------------------------------------------------------------------------
// Helpers. tcgen05 unusable (harness PTX target sm_103, no 'a' suffix) -> the
// tensor path is arch-portable mma.sync (HMMA on sm_103a).
// ---------------------------------------------------------------------------
__device__ __forceinline__ uint32_t smem_u32(const void* p) {
    uint32_t a;
    asm("{ .reg .u64 t; cvta.to.shared.u64 t, %1; cvt.u32.u64 %0, t; }"
        : "=r"(a) : "l"(p));
    return a;
}
__device__ __forceinline__ uint32_t f2tf32(float x) {
    uint32_t r;
    asm("cvt.rna.tf32.f32 %0, %1;" : "=r"(r) : "f"(x));
    return r;
}
__device__ __forceinline__ void mma_tf32(float* c,
                                         const uint32_t* a,
                                         const uint32_t* b) {
    asm volatile(
        "mma.sync.aligned.m16n8k8.row.col.f32.tf32.tf32.f32 "
        "{%0,%1,%2,%3}, {%4,%5,%6,%7}, {%8,%9}, {%0,%1,%2,%3};"
        : "+f"(c[0]), "+f"(c[1]), "+f"(c[2]), "+f"(c[3])
        : "r"(a[0]), "r"(a[1]), "r"(a[2]), "r"(a[3]),
          "r"(b[0]), "r"(b[1]));
}
__device__ __forceinline__ void cpa16(uint32_t saddr, const void* g) {
    asm volatile("cp.async.cg.shared.global [%0], [%1], 16;"
                 :: "r"(saddr), "l"(g) : "memory");
}
#define CP_COMMIT() asm volatile("cp.async.commit_group;" ::: "memory")
#define CP_WAIT(n)  asm volatile("cp.async.wait_group %0;" :: "n"(n) : "memory")

// =============================================================================
// Kernel 0a: convert X -> tf32 bits (RNA) in g_Xt.
// =============================================================================
__global__ void xconv_kernel(const float4* __restrict__ X)
{
    uint4* dst = (uint4*)g_Xt;
#pragma unroll
    for (int j = 0; j < 4; ++j) {
        const size_t i = (size_t)blockIdx.x * 1024 + j * 256 + threadIdx.x;
        float4 v = X[i];
        dst[i] = make_uint4(f2tf32(v.x), f2tf32(v.y), f2tf32(v.z), f2tf32(v.w));
    }
}

// =============================================================================
// Kernel 0b: weight transpose + tf32 convert. Wt[w*512 + n][k] = tf32(W_w[k][n])
// =============================================================================
__global__ void wtrans_kernel(const float* __restrict__ Wq,
                              const float* __restrict__ Wk,
                              const float* __restrict__ Wv,
                              const float* __restrict__ Wr)
{
    __shared__ float t[32][33];
    const int wsel = blockIdx.z;
    const float* W = (wsel == 0) ? Wq : (wsel == 1) ? Wk : (wsel == 2) ? Wv : Wr;
    const int n0 = blockIdx.x * 32, k0 = blockIdx.y * 32;
    const int tx = threadIdx.x, ty = threadIdx.y;
#pragma unroll
    for (int i = 0; i < 32; i += 8)
        t[ty + i][tx] = W[(size_t)(k0 + ty + i) * HDn + n0 + tx];
    __syncthreads();
    uint32_t* Wt = (uint32_t*)g_Wt;
#pragma unroll
    for (int i = 0; i < 32; i += 8)
        Wt[(size_t)(wsel * HDn + n0 + ty + i) * En + k0 + tx] = f2tf32(t[tx][ty + i]);
}

// =============================================================================
// Kernel 1: tf32 mma.sync projection GEMM, 512 threads, C-tile 256x128.
// CTA (bx, bp): rows = batches {2bp, 2bp+1} (contiguous in g_Xt), cols =
// weight (bx>>2), n-tile (bx&3)*128. 16 warps as 4(m) x 4(n), warp tile 64x32.
// K-chunks of 32, 3-stage cp.async pipeline, ONE __syncthreads per chunk.
// Weight tile is amortized over 2 batches -> L2 traffic 4 GB -> 3 GB.
// =============================================================================
constexpr int PP = 36;                           // smem pitch (u32), conflict-free
constexpr int A_U  = 256 * PP;                   // 9216 u32 per A chunk
constexpr int B_U  = 128 * PP;                   // 4608 u32 per B chunk
constexpr int SLOT_U = A_U + B_U;                // 13824 u32 = 55296 B
// 3 slots = 165888 B -> 1 CTA/SM (16 warps)

__global__ __launch_bounds__(512)
void proj_mma(float* __restrict__ out)
{
    extern __shared__ uint32_t sm[];
    const uint32_t sb = smem_u32(sm);

    const int tid  = threadIdx.x;
    const int wid  = tid >> 5;      // 0..15
    const int lane = tid & 31;
    const int g    = lane >> 2;
    const int tg   = lane & 3;
    const int bx   = blockIdx.x;
    const int bp   = blockIdx.y;    // batch pair
    const int w    = bx >> 2;
    const int ncol0 = (bx & 3) * 128;
    const int nbase = bx * 128;

    const int wm = wid >> 2;        // 0..3 -> m base wm*64 (of 256)
    const int wn = wid & 3;         // 0..3 -> n base wn*32

    const float4* A4 = (const float4*)(g_Xt + (size_t)bp * 2 * Sn * En);
    const float4* W4 = (const float4*)g_Wt;

    // cp.async coords: A chunk = 2048 float4 (256 rows x 8), 4/thread;
    //                  B chunk = 1024 float4 (128 rows x 8), 2/thread.
    int arow[4], akq[4], brow[2], bkq[2];
    uint32_t aoff[4], boff[2];
#pragma unroll
    for (int i = 0; i < 4; ++i) {
        const int f4 = tid + i * 512;
        arow[i] = f4 >> 3;
        akq[i]  = f4 & 7;
        aoff[i] = (uint32_t)(arow[i] * PP + akq[i] * 4) * 4;
    }
#pragma unroll
    for (int i = 0; i < 2; ++i) {
        const int f4 = tid + i * 512;
        brow[i] = f4 >> 3;
        bkq[i]  = f4 & 7;
        boff[i] = (uint32_t)(brow[i] * PP + bkq[i] * 4) * 4;
    }

    auto issue = [&](int c) {
        const int slot = c % 3;
        const uint32_t a_s = sb + (uint32_t)slot * SLOT_U * 4;
        const uint32_t b_s = a_s + A_U * 4;
#pragma unroll
        for (int i = 0; i < 4; ++i)
            cpa16(a_s + aoff[i], A4 + arow[i] * 64 + c * 8 + akq[i]);
#pragma unroll
        for (int i = 0; i < 2; ++i)
            cpa16(b_s + boff[i], W4 + (size_t)(nbase + brow[i]) * 64 + c * 8 + bkq[i]);
        CP_COMMIT();
    };

    issue(0);
    issue(1);

    float acc[4][4][4];
#pragma unroll
    for (int mt = 0; mt < 4; ++mt)
#pragma unroll
        for (int nt = 0; nt < 4; ++nt)
#pragma unroll
            for (int j = 0; j < 4; ++j) acc[mt][nt][j] = 0.f;

#pragma unroll 1
    for (int c = 0; c < 8; ++c) {
        const int slot = c % 3;
        if (c < 7) { CP_WAIT(1); } else { CP_WAIT(0); }
        __syncthreads();            // chunk c visible; slot (c-1)%3 reusable
        if (c < 6) issue(c + 2);

        const uint32_t* SA = sm + slot * SLOT_U;
        const uint32_t* SB = SA + A_U;
#pragma unroll
        for (int ks = 0; ks < 4; ++ks) {
            const int k0 = ks * 8;
            uint32_t af[4][4], bf[4][2];
#pragma unroll
            for (int mt = 0; mt < 4; ++mt) {
                const int base = (wm * 64 + mt * 16 + g) * PP + k0 + tg;
                af[mt][0] = SA[base];
                af[mt][1] = SA[base + 8 * PP];
                af[mt][2] = SA[base + 4];
                af[mt][3] = SA[base + 8 * PP + 4];
            }
#pragma unroll
            for (int nt = 0; nt < 4; ++nt) {
                const int nb = (wn * 32 + nt * 8 + g) * PP + k0 + tg;
                bf[nt][0] = SB[nb];
                bf[nt][1] = SB[nb + 4];
            }
#pragma unroll
            for (int mt = 0; mt < 4; ++mt)
#pragma unroll
                for (int nt = 0; nt < 4; ++nt)
                    mma_tf32(acc[mt][nt], af[mt], bf[nt]);
        }
    }

    // Epilogue: rows 0..255 span two batches. Q/K/V as tf32 bits, R as fp32.
#pragma unroll
    for (int mt = 0; mt < 4; ++mt) {
        const int r256 = wm * 64 + mt * 16 + g;
        const int b    = bp * 2 + (r256 >> 7);
        const int row  = r256 & 127;
#pragma unroll
        for (int nt = 0; nt < 4; ++nt) {
            const int cl = wn * 32 + nt * 8 + tg * 2;
            const int nw = ncol0 + cl;
            if (w < 3) {
                float* G = (w == 0) ? g_Q : (w == 1) ? g_K : g_V;
                const int h  = nw >> 6;
                const int d0 = nw & 63;
                uint32_t* dst = (uint32_t*)(G + (((size_t)(b * Hn + h) * Sn + row) * Dn + d0));
                *(uint2*)dst            = make_uint2(f2tf32(acc[mt][nt][0]), f2tf32(acc[mt][nt][1]));
                *(uint2*)(dst + 8 * Dn) = make_uint2(f2tf32(acc[mt][nt][2]), f2tf32(acc[mt][nt][3]));
            } else {
                float* dst = out + ((size_t)b * Sn + row) * HDn + nw;
                *(float2*)dst             = make_float2(acc[mt][nt][0], acc[mt][nt][1]);
                *(float2*)(dst + 8 * HDn) = make_float2(acc[mt][nt][2], acc[mt][nt][3]);
            }
        }
    }
}

// =============================================================================
// Kernel 2: tf32 mma.sync attention (round-7 validated version, unchanged).
// One CTA per (b,h), 256 threads, 8 warps. Q,K,V arrive as tf32 bits.
// Pitches: SQ/SK 68, SV 72, SP 132 — all fragment patterns conflict-free.
// =============================================================================
constexpr int PK  = 68;
constexpr int PV  = 72;
constexpr int PPs = 132;

__global__ __launch_bounds__(256)
void attn_mma(float* __restrict__ out)
{
    extern __shared__ uint32_t smu[];
    uint32_t* SQ = smu;                         // [128][68]
    uint32_t* SK = smu + 128 * PK;              // [128][68]
    uint32_t* SV = smu + 2 * 128 * PK;          // [128][72]
    uint32_t* SP = smu;                         // [128][132] overlays SQ+SK

    const int tid  = threadIdx.x;
    const int wid  = tid >> 5;
    const int lane = tid & 31;
    const int g    = lane >> 2;
    const int tg   = lane & 3;
    const int h = blockIdx.x, b = blockIdx.y;

    const size_t base = ((size_t)(b * Hn + h) * Sn) * Dn;
    const float4* Qg = (const float4*)(g_Q + base);
    const float4* Kg = (const float4*)(g_K + base);
    const float4* Vg = (const float4*)(g_V + base);

    const uint32_t sb = smem_u32(smu);
    const uint32_t SKo = 128 * PK * 4;
    const uint32_t SVo = 2 * 128 * PK * 4;

    // ---- stage Q,K,V raw (already tf32 bits) via cp.async ----
#pragma unroll
    for (int i = 0; i < 8; ++i) {
        const int f4  = tid + i * 256;
        const int row = f4 >> 4;
        const int c4  = (f4 & 15) * 4;
        cpa16(sb + (uint32_t)(row * PK + c4) * 4,       Qg + f4);
        cpa16(sb + SKo + (uint32_t)(row * PK + c4) * 4, Kg + f4);
        cpa16(sb + SVo + (uint32_t)(row * PV + c4) * 4, Vg + f4);
    }
    CP_COMMIT();
    CP_WAIT(0);
    __syncthreads();

    // ---- S = Q K^T ----
    float acc[16][4];
#pragma unroll
    for (int nt = 0; nt < 16; ++nt)
#pragma unroll
        for (int j = 0; j < 4; ++j) acc[nt][j] = 0.f;

    const uint32_t* Arow = SQ + (wid * 16 + g) * PK;
#pragma unroll
    for (int ks = 0; ks < 8; ++ks) {
        const int k0 = ks * 8;
        uint32_t af[4];
        af[0] = Arow[k0 + tg];
        af[1] = Arow[8 * PK + k0 + tg];
        af[2] = Arow[k0 + tg + 4];
        af[3] = Arow[8 * PK + k0 + tg + 4];
#pragma unroll
        for (int nt = 0; nt < 16; ++nt) {
            const uint32_t* Bp = SK + (nt * 8 + g) * PK + k0 + tg;
            uint32_t bf[2] = { Bp[0], Bp[4] };
            mma_tf32(acc[nt], af, bf);
        }
    }

    // ---- softmax rows r0 = wid*16+g, r1 = r0+8 (quad-local shfl) ----
    float m0 = -1e30f, m1 = -1e30f;
#pragma unroll
    for (int nt = 0; nt < 16; ++nt) {
        m0 = fmaxf(m0, fmaxf(acc[nt][0], acc[nt][1]));
        m1 = fmaxf(m1, fmaxf(acc[nt][2], acc[nt][3]));
    }
#pragma unroll
    for (int off = 2; off >= 1; off >>= 1) {
        m0 = fmaxf(m0, __shfl_xor_sync(0xffffffffu, m0, off));
        m1 = fmaxf(m1, __shfl_xor_sync(0xffffffffu, m1, off));
    }
    float s0 = 0.f, s1 = 0.f;
#pragma unroll
    for (int nt = 0; nt < 16; ++nt) {
        acc[nt][0] = __expf(acc[nt][0] - m0);
        acc[nt][1] = __expf(acc[nt][1] - m0);
        acc[nt][2] = __expf(acc[nt][2] - m1);
        acc[nt][3] = __expf(acc[nt][3] - m1);
        s0 += acc[nt][0] + acc[nt][1];
        s1 += acc[nt][2] + acc[nt][3];
    }
#pragma unroll
    for (int off = 2; off >= 1; off >>= 1) {
        s0 += __shfl_xor_sync(0xffffffffu, s0, off);
        s1 += __shfl_xor_sync(0xffffffffu, s1, off);
    }
    const float inv0 = 1.0f / s0;
    const float inv1 = 1.0f / s1;

    __syncthreads();   // all warps done reading SQ/SK before SP overlays them

    const int r0 = wid * 16 + g;
#pragma unroll
    for (int nt = 0; nt < 16; ++nt) {
        const int cl = nt * 8 + tg * 2;
        *(uint2*)&SP[r0 * PPs + cl] =
            make_uint2(f2tf32(acc[nt][0]), f2tf32(acc[nt][1]));
        *(uint2*)&SP[(r0 + 8) * PPs + cl] =
            make_uint2(f2tf32(acc[nt][2]), f2tf32(acc[nt][3]));
    }
    __syncthreads();

    // ---- O = P V ----
    float oacc[8][4];
#pragma unroll
    for (int nt = 0; nt < 8; ++nt)
#pragma unroll
        for (int j = 0; j < 4; ++j) oacc[nt][j] = 0.f;

    const uint32_t* Ap = SP + (wid * 16 + g) * PPs;
#pragma unroll
    for (int ks = 0; ks < 16; ++ks) {
        const int k0 = ks * 8;
        uint32_t af[4];
        af[0] = Ap[k0 + tg];
        af[1] = Ap[8 * PPs + k0 + tg];
        af[2] = Ap[k0 + tg + 4];
        af[3] = Ap[8 * PPs + k0 + tg + 4];
#pragma unroll
        for (int nt = 0; nt < 8; ++nt) {
            uint32_t bf[2];
            bf[0] = SV[(k0 + tg) * PV + nt * 8 + g];
            bf[1] = SV[(k0 + tg + 4) * PV + nt * 8 + g];
            mma_tf32(oacc[nt], af, bf);
        }
    }

    // ---- epilogue: normalize, +residual (fp32 in out), ReLU ----
    float* op = out + ((size_t)b * Sn) * HDn + h * Dn;
#pragma unroll
    for (int nt = 0; nt < 8; ++nt) {
        const int d = nt * 8 + tg * 2;
        float* p0 = op + (size_t)r0 * HDn + d;
        float* p1 = op + (size_t)(r0 + 8) * HDn + d;
        float2 a0 = *(float2*)p0;
        float2 a1 = *(float2*)p1;
        float x0 = a0.x + oacc[nt][0] * inv0;
        float x1 = a0.y + oacc[nt][1] * inv0;
        float x2 = a1.x + oacc[nt][2] * inv1;
        float x3 = a1.y + oacc[nt][3] * inv1;
        *(float2*)p0 = make_float2(fmaxf(x0, 0.f), fmaxf(x1, 0.f));
        *(float2*)p1 = make_float2(fmaxf(x2, 0.f), fmaxf(x3, 0.f));
    }
}

// =============================================================================
extern "C" void kernel_launch(void* const* d_in, const int* in_sizes, int n_in,
                              void* d_out, int out_size)
{
    const float* X  = (const float*)d_in[0];
    const float* Wq = (const float*)d_in[1];
    const float* Wk = (const float*)d_in[2];
    const float* Wv = (const float*)d_in[3];
    const float* Wr = (const float*)d_in[4];
    float* out = (float*)d_out;

    const int proj_smem = 3 * SLOT_U * (int)sizeof(uint32_t);               // 165888
    const int attn_smem = (2 * 128 * PK + 128 * PV) * (int)sizeof(uint32_t); // 106496
    cudaFuncSetAttribute(proj_mma,
                         cudaFuncAttributeMaxDynamicSharedMemorySize, proj_smem);
    cudaFuncSetAttribute(attn_mma,
                         cudaFuncAttributeMaxDynamicSharedMemorySize, attn_smem);

    xconv_kernel<<<8192, 256>>>((const float4*)X);
    wtrans_kernel<<<dim3(16, 8, 4), dim3(32, 8)>>>(Wq, Wk, Wv, Wr);
    proj_mma<<<dim3(16, 512), 512, proj_smem>>>(out);
    attn_mma<<<dim3(8, 1024), 256, attn_smem>>>(out);
}

// round 11
// speedup vs baseline: 1.2883x; 1.1195x over previous
#include <cuda_runtime.h>
#include <cstdint>

// Problem constants
#define Bn  1024
#define Sn  128
#define En  256
#define Hn  8
#define Dn  64
#define HDn 512

// Scratch (tf32 bit patterns in float arrays): Q,K,V per-(b,h) [128x64] tiles,
// Xt = pre-converted inputs, Wt = transposed + converted weights.
__device__ float g_Q[67108864];
__device__ float g_K[67108864];
__device__ float g_V[67108864];
__device__ float g_Xt[33554432];
__device__ float g_Wt[2048 * 256];

// ---------------------------------------------------------------------------
// Helpers. tcgen05 unusable (harness PTX target sm_103, no 'a' suffix) -> the
// tensor path is arch-portable mma.sync (HMMA on sm_103a).
// ---------------------------------------------------------------------------
__device__ __forceinline__ uint32_t smem_u32(const void* p) {
    uint32_t a;
    asm("{ .reg .u64 t; cvta.to.shared.u64 t, %1; cvt.u32.u64 %0, t; }"
        : "=r"(a) : "l"(p));
    return a;
}
__device__ __forceinline__ uint32_t f2tf32(float x) {
    uint32_t r;
    asm("cvt.rna.tf32.f32 %0, %1;" : "=r"(r) : "f"(x));
    return r;
}
__device__ __forceinline__ void mma_tf32(float* c,
                                         const uint32_t* a,
                                         const uint32_t* b) {
    asm volatile(
        "mma.sync.aligned.m16n8k8.row.col.f32.tf32.tf32.f32 "
        "{%0,%1,%2,%3}, {%4,%5,%6,%7}, {%8,%9}, {%0,%1,%2,%3};"
        : "+f"(c[0]), "+f"(c[1]), "+f"(c[2]), "+f"(c[3])
        : "r"(a[0]), "r"(a[1]), "r"(a[2]), "r"(a[3]),
          "r"(b[0]), "r"(b[1]));
}
__device__ __forceinline__ void cpa16(uint32_t saddr, const void* g) {
    asm volatile("cp.async.cg.shared.global [%0], [%1], 16;"
                 :: "r"(saddr), "l"(g) : "memory");
}
#define CP_COMMIT() asm volatile("cp.async.commit_group;" ::: "memory")
#define CP_WAIT(n)  asm volatile("cp.async.wait_group %0;" :: "n"(n) : "memory")

// =============================================================================
// Kernel 0a: convert X -> tf32 bits (RNA) in g_Xt.
// =============================================================================
__global__ void xconv_kernel(const float4* __restrict__ X)
{
    uint4* dst = (uint4*)g_Xt;
#pragma unroll
    for (int j = 0; j < 4; ++j) {
        const size_t i = (size_t)blockIdx.x * 1024 + j * 256 + threadIdx.x;
        float4 v = X[i];
        dst[i] = make_uint4(f2tf32(v.x), f2tf32(v.y), f2tf32(v.z), f2tf32(v.w));
    }
}

// =============================================================================
// Kernel 0b: weight transpose + tf32 convert. Wt[w*512 + n][k] = tf32(W_w[k][n])
// =============================================================================
__global__ void wtrans_kernel(const float* __restrict__ Wq,
                              const float* __restrict__ Wk,
                              const float* __restrict__ Wv,
                              const float* __restrict__ Wr)
{
    __shared__ float t[32][33];
    const int wsel = blockIdx.z;
    const float* W = (wsel == 0) ? Wq : (wsel == 1) ? Wk : (wsel == 2) ? Wv : Wr;
    const int n0 = blockIdx.x * 32, k0 = blockIdx.y * 32;
    const int tx = threadIdx.x, ty = threadIdx.y;
#pragma unroll
    for (int i = 0; i < 32; i += 8)
        t[ty + i][tx] = W[(size_t)(k0 + ty + i) * HDn + n0 + tx];
    __syncthreads();
    uint32_t* Wt = (uint32_t*)g_Wt;
#pragma unroll
    for (int i = 0; i < 32; i += 8)
        Wt[(size_t)(wsel * HDn + n0 + ty + i) * En + k0 + tx] = f2tf32(t[tx][ty + i]);
}

// =============================================================================
// Kernel 1: tf32 mma.sync projection GEMM. 128 threads, 4 warps, C-tile
// 128x128, warp grid 2(m) x 2(n) -> warp tile 64x64 (4mt x 8nt fragments).
// Rationale: 64x64 warp tiles halve smem-read amplification (A read by 2
// warps instead of 4) -> crossbar traffic/set 16K -> 12K cyc, below the
// 16.4K-cyc tensor floor. 2 CTAs/SM preserved (regs ~180x128x2 = 46K;
// smem 110592 x 2 = 221KB). Same 3-stage cp.async, one sync per chunk.
// Accumulation order per output element is unchanged -> bit-identical.
// =============================================================================
constexpr int PP = 36;                       // smem pitch (u32), conflict-free
constexpr int CHUNK_U = 128 * PP;            // 4608 u32 per matrix per chunk
constexpr int SLOT_U  = 2 * CHUNK_U;         // 9216 u32 = 36864 B

__global__ __launch_bounds__(128)
void proj_mma(float* __restrict__ out)
{
    extern __shared__ uint32_t sm[];
    const uint32_t sb = smem_u32(sm);

    const int tid  = threadIdx.x;
    const int wid  = tid >> 5;      // 0..3
    const int lane = tid & 31;
    const int g    = lane >> 2;
    const int tg   = lane & 3;
    const int bx   = blockIdx.x;
    const int b    = blockIdx.y;
    const int w    = bx >> 2;
    const int ncol0 = (bx & 3) * 128;
    const int nbase = bx * 128;

    const int wm = wid >> 1;        // 0..1 -> m base wm*64
    const int wn = wid & 1;         // 0..1 -> n base wn*64

    const float4* A4 = (const float4*)(g_Xt + (size_t)b * Sn * En);
    const float4* W4 = (const float4*)g_Wt;

    // cp.async coords: A chunk = 1024 float4 (128 rows x 8), 8/thread; B same.
    int lrow[8], lkq[8];
    uint32_t soff[8];
#pragma unroll
    for (int i = 0; i < 8; ++i) {
        const int f4 = tid + i * 128;
        lrow[i] = f4 >> 3;
        lkq[i]  = f4 & 7;
        soff[i] = (uint32_t)(lrow[i] * PP + lkq[i] * 4) * 4;
    }

    auto issue = [&](int c) {
        const int slot = c % 3;
        const uint32_t a_s = sb + (uint32_t)slot * SLOT_U * 4;
        const uint32_t b_s = a_s + CHUNK_U * 4;
#pragma unroll
        for (int i = 0; i < 8; ++i) {
            cpa16(a_s + soff[i], A4 + lrow[i] * 64 + c * 8 + lkq[i]);
            cpa16(b_s + soff[i], W4 + (size_t)(nbase + lrow[i]) * 64 + c * 8 + lkq[i]);
        }
        CP_COMMIT();
    };

    issue(0);
    issue(1);

    float acc[4][8][4];
#pragma unroll
    for (int mt = 0; mt < 4; ++mt)
#pragma unroll
        for (int nt = 0; nt < 8; ++nt)
#pragma unroll
            for (int j = 0; j < 4; ++j) acc[mt][nt][j] = 0.f;

#pragma unroll 1
    for (int c = 0; c < 8; ++c) {
        const int slot = c % 3;
        if (c < 7) { CP_WAIT(1); } else { CP_WAIT(0); }
        __syncthreads();            // chunk c visible; slot (c-1)%3 reusable
        if (c < 6) issue(c + 2);

        const uint32_t* SA = sm + slot * SLOT_U;
        const uint32_t* SB = SA + CHUNK_U;
#pragma unroll
        for (int ks = 0; ks < 4; ++ks) {
            const int k0 = ks * 8;
            uint32_t af[4][4], bf[8][2];
#pragma unroll
            for (int mt = 0; mt < 4; ++mt) {
                const int base = (wm * 64 + mt * 16 + g) * PP + k0 + tg;
                af[mt][0] = SA[base];
                af[mt][1] = SA[base + 8 * PP];
                af[mt][2] = SA[base + 4];
                af[mt][3] = SA[base + 8 * PP + 4];
            }
#pragma unroll
            for (int nt = 0; nt < 8; ++nt) {
                const int nb = (wn * 64 + nt * 8 + g) * PP + k0 + tg;
                bf[nt][0] = SB[nb];
                bf[nt][1] = SB[nb + 4];
            }
#pragma unroll
            for (int mt = 0; mt < 4; ++mt)
#pragma unroll
                for (int nt = 0; nt < 8; ++nt)
                    mma_tf32(acc[mt][nt], af[mt], bf[nt]);
        }
    }

    // Epilogue: Q/K/V as tf32 bits, R as fp32.
#pragma unroll
    for (int mt = 0; mt < 4; ++mt) {
        const int row = wm * 64 + mt * 16 + g;
#pragma unroll
        for (int nt = 0; nt < 8; ++nt) {
            const int cl = wn * 64 + nt * 8 + tg * 2;
            const int nw = ncol0 + cl;
            if (w < 3) {
                float* G = (w == 0) ? g_Q : (w == 1) ? g_K : g_V;
                const int h  = nw >> 6;
                const int d0 = nw & 63;
                uint32_t* dst = (uint32_t*)(G + (((size_t)(b * Hn + h) * Sn + row) * Dn + d0));
                *(uint2*)dst            = make_uint2(f2tf32(acc[mt][nt][0]), f2tf32(acc[mt][nt][1]));
                *(uint2*)(dst + 8 * Dn) = make_uint2(f2tf32(acc[mt][nt][2]), f2tf32(acc[mt][nt][3]));
            } else {
                float* dst = out + ((size_t)b * Sn + row) * HDn + nw;
                *(float2*)dst             = make_float2(acc[mt][nt][0], acc[mt][nt][1]);
                *(float2*)(dst + 8 * HDn) = make_float2(acc[mt][nt][2], acc[mt][nt][3]);
            }
        }
    }
}

// =============================================================================
// Kernel 2: tf32 mma.sync attention. One CTA per (b,h), 256 threads, 8 warps.
// Changes vs round 7: (a) batch order reversed so the first attn batches hit
// proj's still-L2-resident tail; (b) residual out-values prefetched into
// registers right after softmax -> LDG latency hides under the PV MMA loop.
// Arithmetic identical to round 7.
// =============================================================================
constexpr int PK  = 68;
constexpr int PV  = 72;
constexpr int PPs = 132;

__global__ __launch_bounds__(256)
void attn_mma(float* __restrict__ out)
{
    extern __shared__ uint32_t smu[];
    uint32_t* SQ = smu;                         // [128][68]
    uint32_t* SK = smu + 128 * PK;              // [128][68]
    uint32_t* SV = smu + 2 * 128 * PK;          // [128][72]
    uint32_t* SP = smu;                         // [128][132] overlays SQ+SK

    const int tid  = threadIdx.x;
    const int wid  = tid >> 5;
    const int lane = tid & 31;
    const int g    = lane >> 2;
    const int tg   = lane & 3;
    const int h = blockIdx.x;
    const int b = (Bn - 1) - blockIdx.y;        // reversed: reuse proj's L2 tail

    const size_t base = ((size_t)(b * Hn + h) * Sn) * Dn;
    const float4* Qg = (const float4*)(g_Q + base);
    const float4* Kg = (const float4*)(g_K + base);
    const float4* Vg = (const float4*)(g_V + base);

    const uint32_t sb = smem_u32(smu);
    const uint32_t SKo = 128 * PK * 4;
    const uint32_t SVo = 2 * 128 * PK * 4;

    // ---- stage Q,K,V raw (already tf32 bits) via cp.async ----
#pragma unroll
    for (int i = 0; i < 8; ++i) {
        const int f4  = tid + i * 256;
        const int row = f4 >> 4;
        const int c4  = (f4 & 15) * 4;
        cpa16(sb + (uint32_t)(row * PK + c4) * 4,       Qg + f4);
        cpa16(sb + SKo + (uint32_t)(row * PK + c4) * 4, Kg + f4);
        cpa16(sb + SVo + (uint32_t)(row * PV + c4) * 4, Vg + f4);
    }
    CP_COMMIT();
    CP_WAIT(0);
    __syncthreads();

    // ---- S = Q K^T ----
    float acc[16][4];
#pragma unroll
    for (int nt = 0; nt < 16; ++nt)
#pragma unroll
        for (int j = 0; j < 4; ++j) acc[nt][j] = 0.f;

    const uint32_t* Arow = SQ + (wid * 16 + g) * PK;
#pragma unroll
    for (int ks = 0; ks < 8; ++ks) {
        const int k0 = ks * 8;
        uint32_t af[4];
        af[0] = Arow[k0 + tg];
        af[1] = Arow[8 * PK + k0 + tg];
        af[2] = Arow[k0 + tg + 4];
        af[3] = Arow[8 * PK + k0 + tg + 4];
#pragma unroll
        for (int nt = 0; nt < 16; ++nt) {
            const uint32_t* Bp = SK + (nt * 8 + g) * PK + k0 + tg;
            uint32_t bf[2] = { Bp[0], Bp[4] };
            mma_tf32(acc[nt], af, bf);
        }
    }

    // ---- softmax rows r0 = wid*16+g, r1 = r0+8 (quad-local shfl) ----
    const int r0 = wid * 16 + g;
    float m0 = -1e30f, m1 = -1e30f;
#pragma unroll
    for (int nt = 0; nt < 16; ++nt) {
        m0 = fmaxf(m0, fmaxf(acc[nt][0], acc[nt][1]));
        m1 = fmaxf(m1, fmaxf(acc[nt][2], acc[nt][3]));
    }
#pragma unroll
    for (int off = 2; off >= 1; off >>= 1) {
        m0 = fmaxf(m0, __shfl_xor_sync(0xffffffffu, m0, off));
        m1 = fmaxf(m1, __shfl_xor_sync(0xffffffffu, m1, off));
    }
    float s0 = 0.f, s1 = 0.f;
#pragma unroll
    for (int nt = 0; nt < 16; ++nt) {
        acc[nt][0] = __expf(acc[nt][0] - m0);
        acc[nt][1] = __expf(acc[nt][1] - m0);
        acc[nt][2] = __expf(acc[nt][2] - m1);
        acc[nt][3] = __expf(acc[nt][3] - m1);
        s0 += acc[nt][0] + acc[nt][1];
        s1 += acc[nt][2] + acc[nt][3];
    }
#pragma unroll
    for (int off = 2; off >= 1; off >>= 1) {
        s0 += __shfl_xor_sync(0xffffffffu, s0, off);
        s1 += __shfl_xor_sync(0xffffffffu, s1, off);
    }
    const float inv0 = 1.0f / s0;
    const float inv1 = 1.0f / s1;

    // ---- prefetch residual (hides LDG latency under the PV loop) ----
    float* op = out + ((size_t)b * Sn) * HDn + h * Dn;
    float2 res0[8], res1[8];
#pragma unroll
    for (int nt = 0; nt < 8; ++nt) {
        const int d = nt * 8 + tg * 2;
        res0[nt] = *(const float2*)(op + (size_t)r0 * HDn + d);
        res1[nt] = *(const float2*)(op + (size_t)(r0 + 8) * HDn + d);
    }

    __syncthreads();   // all warps done reading SQ/SK before SP overlays them

#pragma unroll
    for (int nt = 0; nt < 16; ++nt) {
        const int cl = nt * 8 + tg * 2;
        *(uint2*)&SP[r0 * PPs + cl] =
            make_uint2(f2tf32(acc[nt][0]), f2tf32(acc[nt][1]));
        *(uint2*)&SP[(r0 + 8) * PPs + cl] =
            make_uint2(f2tf32(acc[nt][2]), f2tf32(acc[nt][3]));
    }
    __syncthreads();

    // ---- O = P V ----
    float oacc[8][4];
#pragma unroll
    for (int nt = 0; nt < 8; ++nt)
#pragma unroll
        for (int j = 0; j < 4; ++j) oacc[nt][j] = 0.f;

    const uint32_t* Ap = SP + (wid * 16 + g) * PPs;
#pragma unroll
    for (int ks = 0; ks < 16; ++ks) {
        const int k0 = ks * 8;
        uint32_t af[4];
        af[0] = Ap[k0 + tg];
        af[1] = Ap[8 * PPs + k0 + tg];
        af[2] = Ap[k0 + tg + 4];
        af[3] = Ap[8 * PPs + k0 + tg + 4];
#pragma unroll
        for (int nt = 0; nt < 8; ++nt) {
            uint32_t bf[2];
            bf[0] = SV[(k0 + tg) * PV + nt * 8 + g];
            bf[1] = SV[(k0 + tg + 4) * PV + nt * 8 + g];
            mma_tf32(oacc[nt], af, bf);
        }
    }

    // ---- epilogue: normalize, +residual (prefetched), ReLU ----
#pragma unroll
    for (int nt = 0; nt < 8; ++nt) {
        const int d = nt * 8 + tg * 2;
        float x0 = res0[nt].x + oacc[nt][0] * inv0;
        float x1 = res0[nt].y + oacc[nt][1] * inv0;
        float x2 = res1[nt].x + oacc[nt][2] * inv1;
        float x3 = res1[nt].y + oacc[nt][3] * inv1;
        *(float2*)(op + (size_t)r0 * HDn + d) =
            make_float2(fmaxf(x0, 0.f), fmaxf(x1, 0.f));
        *(float2*)(op + (size_t)(r0 + 8) * HDn + d) =
            make_float2(fmaxf(x2, 0.f), fmaxf(x3, 0.f));
    }
}

// =============================================================================
extern "C" void kernel_launch(void* const* d_in, const int* in_sizes, int n_in,
                              void* d_out, int out_size)
{
    const float* X  = (const float*)d_in[0];
    const float* Wq = (const float*)d_in[1];
    const float* Wk = (const float*)d_in[2];
    const float* Wv = (const float*)d_in[3];
    const float* Wr = (const float*)d_in[4];
    float* out = (float*)d_out;

    const int proj_smem = 3 * SLOT_U * (int)sizeof(uint32_t);                // 110592
    const int attn_smem = (2 * 128 * PK + 128 * PV) * (int)sizeof(uint32_t); // 106496
    cudaFuncSetAttribute(proj_mma,
                         cudaFuncAttributeMaxDynamicSharedMemorySize, proj_smem);
    cudaFuncSetAttribute(attn_mma,
                         cudaFuncAttributeMaxDynamicSharedMemorySize, attn_smem);

    xconv_kernel<<<8192, 256>>>((const float4*)X);
    wtrans_kernel<<<dim3(16, 8, 4), dim3(32, 8)>>>(Wq, Wk, Wv, Wr);
    proj_mma<<<dim3(16, 1024), 128, proj_smem>>>(out);
    attn_mma<<<dim3(8, 1024), 256, attn_smem>>>(out);
}